// round 11
// baseline (speedup 1.0000x reference)
#include <cuda_runtime.h>
#include <cstdint>

// Who2com reduces exactly to: out = bevs (softmax over axis 1 followed by
// sum over axis 1 is identically 1.0; everything upstream only feeds the
// softmax logits). Kernel = 84 MB copy.
//
// Model after R9/R10: L2 state does NOT persist usefully across graph
// replays; the one proven win (R7, -2us) is evict_last STORES deferring dst
// writebacks past the kernel's critical path within each replay. Keep that,
// and tighten the two untouched knobs:
//  - flat batch of 16 independent LDG.128s per thread before any store
//    (max MLP, no loop reissue bubbles),
//  - 1280 blocks x 256 thr x 8 vec8/thread = 2,621,440 exactly (fewer waves,
//    no ragged tail vs 2560 blocks).

__global__ __launch_bounds__(256) void who2com_copy_kernel(
    const float4* __restrict__ src, float* __restrict__ dst)
{
    const int nthreads = gridDim.x * blockDim.x;          // 327,680
    const int tid = blockIdx.x * blockDim.x + threadIdx.x;

    // 8 vec8 chunks per thread = 16 float4 loads, all independent, batched.
    float4 v[16];
    #pragma unroll
    for (int k = 0; k < 8; k++) {
        const int c = tid + k * nthreads;                 // vec8 index
        v[2 * k + 0] = src[2 * c + 0];
        v[2 * k + 1] = src[2 * c + 1];
    }

    #pragma unroll
    for (int k = 0; k < 8; k++) {
        const int c = tid + k * nthreads;
        const float4 a = v[2 * k + 0];
        const float4 b = v[2 * k + 1];
        // 256-bit store with L2::evict_last: dirty lines park in L2 and
        // write back after the kernel, off the critical path (R7-proven).
        asm volatile(
            "st.global.L2::evict_last.v8.f32 [%0], "
            "{%1, %2, %3, %4, %5, %6, %7, %8};"
            :: "l"(dst + (size_t)c * 8),
               "f"(a.x), "f"(a.y), "f"(a.z), "f"(a.w),
               "f"(b.x), "f"(b.y), "f"(b.z), "f"(b.w)
            : "memory");
    }
}

extern "C" void kernel_launch(void* const* d_in, const int* in_sizes, int n_in,
                              void* d_out, int out_size)
{
    const float4* src = (const float4*)d_in[0];   // bevs: [1,4,80,256,256] fp32
    float* dst = (float*)d_out;

    // out_size = 20,971,520 floats = 2,621,440 vec8 = 327,680 threads * 8.
    const int threads = 256;
    const int blocks = 1280;
    who2com_copy_kernel<<<blocks, threads>>>(src, dst);
}

// round 12
// speedup vs baseline: 1.0022x; 1.0022x over previous
#include <cuda_runtime.h>
#include <cstdint>

// Who2com reduces exactly to: out = bevs (softmax over axis 1 followed by
// sum over axis 1 is identically 1.0; everything upstream only feeds the
// softmax logits). Kernel = 84 MB copy.
//
// Locked-in model (R1-R11):
//  - ~5 TB/s is an engine-independent wall for mixed read+write streams
//    (SM copy == CE memcpy).
//  - L2 state does not persist across graph replays (pinning schemes all
//    regressed).
//  - The ONE winning mechanism: evict_last STORES park dirty lines in L2 and
//    write back after the kernel, off the critical path (R7: 29.2 -> 27.1).
// This round = R7's exact proven geometry (2560 x 256, 4 vec8/thread) with
// one minimal delta: plain 256-bit loads (LDG.256, no cache policy) to halve
// load instruction count / L1tex wavefronts, symmetric with STG.256.

__global__ __launch_bounds__(256) void who2com_copy_kernel(
    const float* __restrict__ src, float* __restrict__ dst)
{
    const int nthreads = gridDim.x * blockDim.x;          // 655,360
    const int tid = blockIdx.x * blockDim.x + threadIdx.x;

    #pragma unroll
    for (int k = 0; k < 4; k++) {
        const int c = tid + k * nthreads;                 // vec8 index
        float v0, v1, v2, v3, v4, v5, v6, v7;
        // Plain 256-bit load (default cache policy -- the fast path).
        asm volatile(
            "ld.global.v8.f32 {%0, %1, %2, %3, %4, %5, %6, %7}, [%8];"
            : "=f"(v0), "=f"(v1), "=f"(v2), "=f"(v3),
              "=f"(v4), "=f"(v5), "=f"(v6), "=f"(v7)
            : "l"(src + (size_t)c * 8));
        // 256-bit store with L2::evict_last: writebacks deferred past the
        // kernel's critical path (the proven R7 mechanism).
        asm volatile(
            "st.global.L2::evict_last.v8.f32 [%0], "
            "{%1, %2, %3, %4, %5, %6, %7, %8};"
            :: "l"(dst + (size_t)c * 8),
               "f"(v0), "f"(v1), "f"(v2), "f"(v3),
               "f"(v4), "f"(v5), "f"(v6), "f"(v7)
            : "memory");
    }
}

extern "C" void kernel_launch(void* const* d_in, const int* in_sizes, int n_in,
                              void* d_out, int out_size)
{
    const float* src = (const float*)d_in[0];   // bevs: [1,4,80,256,256] fp32
    float* dst = (float*)d_out;

    // out_size = 20,971,520 floats = 2,621,440 vec8 = 655,360 threads * 4.
    const int threads = 256;
    const int blocks = 2560;
    who2com_copy_kernel<<<blocks, threads>>>(src, dst);
}

// round 13
// speedup vs baseline: 1.0849x; 1.0825x over previous
#include <cuda_runtime.h>
#include <cstdint>

// Who2com reduces exactly to: out = bevs (softmax over axis 1 followed by
// sum over axis 1 is identically 1.0; everything upstream only feeds the
// softmax logits). Kernel = 84 MB copy.
//
// FINAL configuration (R7, re-benched for reproducibility). Locked-in model
// from rounds 1-12:
//  - ~5 TB/s is an engine-independent wall for mixed read+write DRAM streams
//    (SM copy == CE memcpy node).
//  - Loads must be plain LDG.128: every other load form (evict_last, .cs,
//    nc.v8, plain v8/LDG.256) measurably regresses.
//  - Stores: STG.256 with L2::evict_last wins (29.2 -> 27.1 us): dirty lines
//    park in L2 and write back after the kernel, off the critical path.
//  - Cross-replay L2 residency does not exist on this part; pinning and
//    compare-and-skip schemes all regressed.
//  - Geometry: 2560 blocks x 256 threads, 4 vec8/thread (exact division of
//    2,621,440 vec8 chunks).

__global__ __launch_bounds__(256) void who2com_copy_kernel(
    const float4* __restrict__ src, float* __restrict__ dst)
{
    const int nthreads = gridDim.x * blockDim.x;          // 655,360
    const int tid = blockIdx.x * blockDim.x + threadIdx.x;

    #pragma unroll
    for (int k = 0; k < 4; k++) {
        const int c = tid + k * nthreads;                 // vec8 index
        // Plain 128-bit loads: the proven fastest read path.
        float4 a = src[2 * c + 0];
        float4 b = src[2 * c + 1];
        // 256-bit store with L2::evict_last: writebacks deferred past the
        // kernel's critical path (the one mechanism that measurably wins).
        asm volatile(
            "st.global.L2::evict_last.v8.f32 [%0], "
            "{%1, %2, %3, %4, %5, %6, %7, %8};"
            :: "l"(dst + (size_t)c * 8),
               "f"(a.x), "f"(a.y), "f"(a.z), "f"(a.w),
               "f"(b.x), "f"(b.y), "f"(b.z), "f"(b.w)
            : "memory");
    }
}

extern "C" void kernel_launch(void* const* d_in, const int* in_sizes, int n_in,
                              void* d_out, int out_size)
{
    const float4* src = (const float4*)d_in[0];   // bevs: [1,4,80,256,256] fp32
    float* dst = (float*)d_out;

    // out_size = 20,971,520 floats = 2,621,440 vec8 = 655,360 threads * 4.
    const int threads = 256;
    const int blocks = 2560;
    who2com_copy_kernel<<<blocks, threads>>>(src, dst);
}